// round 3
// baseline (speedup 1.0000x reference)
#include <cuda_runtime.h>
#include <cuda_bf16.h>

#define OUT_SZ 7
#define NCELL (OUT_SZ * OUT_SZ)      // 49
#define NCH 256
#define NQ (NCH / 4)                 // 64 float4 per channel row
#define SLOTS 4                      // cells per block
#define NGROUPS ((NCELL + SLOTS - 1) / SLOTS)   // 13

__global__ __launch_bounds__(NQ * SLOTS, 8)
void roialign_kernel(const float* __restrict__ p2,
                     const float* __restrict__ p3,
                     const float* __restrict__ p4,
                     const float* __restrict__ p5,
                     const float* __restrict__ rois,
                     float* __restrict__ out)
{
    int roi = blockIdx.x;

    int tid  = threadIdx.x;
    int cq   = tid & (NQ - 1);       // channel quad 0..63
    int slot = tid >> 6;             // 0..3
    int cell = blockIdx.y * SLOTS + slot;
    if (cell >= NCELL) return;

    // rois row: [batch, x1, y1, x2, y2]
    const float* r = rois + (size_t)roi * 5;
    float bf  = __ldg(r + 0);
    float rx1 = __ldg(r + 1), ry1 = __ldg(r + 2);
    float rx2 = __ldg(r + 3), ry2 = __ldg(r + 4);
    int b = (int)bf;

    float roi_w = rx2 - rx1;
    float roi_h = ry2 - ry1;
    float lvl = 4.0f + log2f(sqrtf(roi_h * roi_w) / 224.0f);
    int level = (int)rintf(lvl);
    level = level < 2 ? 2 : (level > 5 ? 5 : level);

    const float* fm;
    int H;            // H == W at every level
    float inv_stride;
    switch (level) {
        case 2: fm = p2; H = 256; inv_stride = 1.0f / 4.0f;  break;
        case 3: fm = p3; H = 128; inv_stride = 1.0f / 8.0f;  break;
        case 4: fm = p4; H = 64;  inv_stride = 1.0f / 16.0f; break;
        default: fm = p5; H = 32; inv_stride = 1.0f / 32.0f; break;
    }
    int W = H;
    float Hm1 = (float)(H - 1);
    float Wm1 = (float)(W - 1);

    // crop_and_resize reads boxes as [y1,x1,y2,x2]; roi_align passes
    // [x1,y1,x2,y2]*(1/stride). So box_y1 = rx1/stride, box_x1 = ry1/stride.
    float by1 = rx1 * inv_stride;
    float bx1 = ry1 * inv_stride;
    float by2 = rx2 * inv_stride;
    float bx2 = ry2 * inv_stride;

    float h_scale = (by2 - by1) * Hm1 * (1.0f / (float)(OUT_SZ - 1));
    float w_scale = (bx2 - bx1) * Wm1 * (1.0f / (float)(OUT_SZ - 1));
    float y_base = by1 * Hm1;
    float x_base = bx1 * Wm1;

    int i = cell / OUT_SZ;
    int j = cell - i * OUT_SZ;

    float in_y = fmaf((float)i, h_scale, y_base);
    float in_x = fmaf((float)j, w_scale, x_base);
    bool valid = (in_y >= 0.0f) & (in_y <= Hm1) &
                 (in_x >= 0.0f) & (in_x <= Wm1);

    const float4* fm_b = (const float4*)(fm + (size_t)b * H * W * NCH);
    float4* out_ptr = (float4*)(out + (size_t)roi * NCELL * NCH) + cell * NQ + cq;

    float4 v = make_float4(0.f, 0.f, 0.f, 0.f);
    if (valid) {
        float fy = floorf(in_y);
        float fx = floorf(in_x);
        float ly = in_y - fy;
        float lx = in_x - fx;
        // in-range ⇒ floor in [0,H-1]; ceil only needs upper clip
        int y0 = (int)fy;
        int x0 = (int)fx;
        int yc = (int)fminf(ceilf(in_y), Hm1);
        int xc = (int)fminf(ceilf(in_x), Wm1);

        const float4* row0 = fm_b + (size_t)y0 * W * NQ;
        const float4* row1 = fm_b + (size_t)yc * W * NQ;
        float4 tl = __ldg(row0 + x0 * NQ + cq);
        float4 tr = __ldg(row0 + xc * NQ + cq);
        float4 bl = __ldg(row1 + x0 * NQ + cq);
        float4 br = __ldg(row1 + xc * NQ + cq);

        float4 top, bot;
        top.x = fmaf(tr.x - tl.x, lx, tl.x);
        top.y = fmaf(tr.y - tl.y, lx, tl.y);
        top.z = fmaf(tr.z - tl.z, lx, tl.z);
        top.w = fmaf(tr.w - tl.w, lx, tl.w);
        bot.x = fmaf(br.x - bl.x, lx, bl.x);
        bot.y = fmaf(br.y - bl.y, lx, bl.y);
        bot.z = fmaf(br.z - bl.z, lx, bl.z);
        bot.w = fmaf(br.w - bl.w, lx, bl.w);
        v.x = fmaf(bot.x - top.x, ly, top.x);
        v.y = fmaf(bot.y - top.y, ly, top.y);
        v.z = fmaf(bot.z - top.z, ly, top.z);
        v.w = fmaf(bot.w - top.w, ly, top.w);
    }
    *out_ptr = v;
}

extern "C" void kernel_launch(void* const* d_in, const int* in_sizes, int n_in,
                              void* d_out, int out_size)
{
    const float* p2   = (const float*)d_in[0];
    const float* p3   = (const float*)d_in[1];
    const float* p4   = (const float*)d_in[2];
    const float* p5   = (const float*)d_in[3];
    const float* rois = (const float*)d_in[4];
    float* out = (float*)d_out;
    int n_rois = in_sizes[4] / 5;

    dim3 grid(n_rois, NGROUPS);
    roialign_kernel<<<grid, NQ * SLOTS>>>(p2, p3, p4, p5, rois, out);
}

// round 4
// speedup vs baseline: 1.2527x; 1.2527x over previous
#include <cuda_runtime.h>
#include <cuda_bf16.h>

#define OUT_SZ 7
#define NCELL (OUT_SZ * OUT_SZ)      // 49
#define NCH 256
#define NQ (NCH / 4)                 // 64 float4 per channel row
#define SLOTS 4                      // cells per block
#define NGROUPS ((NCELL + SLOTS - 1) / SLOTS)   // 13

struct RoiParams {
    const float4* fm_b;   // feature map base for this roi's batch & level
    float y_base, x_base;
    float h_scale, w_scale;
    float Hm1;            // H-1 == W-1
    int   W;
};

__global__ __launch_bounds__(NQ * SLOTS, 8)
void roialign_kernel(const float* __restrict__ p2,
                     const float* __restrict__ p3,
                     const float* __restrict__ p4,
                     const float* __restrict__ p5,
                     const float* __restrict__ rois,
                     float* __restrict__ out)
{
    __shared__ RoiParams sp;

    int roi = blockIdx.x;
    int tid = threadIdx.x;

    if (tid == 0) {
        // rois row: [batch, x1, y1, x2, y2]
        const float* r = rois + (size_t)roi * 5;
        float bf  = __ldg(r + 0);
        float rx1 = __ldg(r + 1), ry1 = __ldg(r + 2);
        float rx2 = __ldg(r + 3), ry2 = __ldg(r + 4);
        int b = (int)bf;

        float roi_w = rx2 - rx1;
        float roi_h = ry2 - ry1;
        float lvl = 4.0f + log2f(sqrtf(roi_h * roi_w) / 224.0f);
        int level = (int)rintf(lvl);
        level = level < 2 ? 2 : (level > 5 ? 5 : level);

        const float* fm;
        int H;
        float inv_stride;
        switch (level) {
            case 2: fm = p2; H = 256; inv_stride = 1.0f / 4.0f;  break;
            case 3: fm = p3; H = 128; inv_stride = 1.0f / 8.0f;  break;
            case 4: fm = p4; H = 64;  inv_stride = 1.0f / 16.0f; break;
            default: fm = p5; H = 32; inv_stride = 1.0f / 32.0f; break;
        }
        float Hm1 = (float)(H - 1);

        // crop_and_resize reads boxes as [y1,x1,y2,x2]; roi_align passes
        // [x1,y1,x2,y2]*(1/stride). So box_y1 = rx1/stride, box_x1 = ry1/stride.
        float by1 = rx1 * inv_stride;
        float bx1 = ry1 * inv_stride;
        float by2 = rx2 * inv_stride;
        float bx2 = ry2 * inv_stride;

        sp.h_scale = (by2 - by1) * Hm1 * (1.0f / (float)(OUT_SZ - 1));
        sp.w_scale = (bx2 - bx1) * Hm1 * (1.0f / (float)(OUT_SZ - 1));
        sp.y_base  = by1 * Hm1;
        sp.x_base  = bx1 * Hm1;
        sp.Hm1     = Hm1;
        sp.W       = H;
        sp.fm_b    = (const float4*)(fm + (size_t)b * H * H * NCH);
    }
    __syncthreads();

    int cq   = tid & (NQ - 1);       // channel quad 0..63
    int slot = tid >> 6;             // 0..3
    int cell = blockIdx.y * SLOTS + slot;
    if (cell >= NCELL) return;

    int i = cell / OUT_SZ;
    int j = cell - i * OUT_SZ;

    float Hm1 = sp.Hm1;
    int   W   = sp.W;
    float in_y = fmaf((float)i, sp.h_scale, sp.y_base);
    float in_x = fmaf((float)j, sp.w_scale, sp.x_base);
    bool valid = (in_y >= 0.0f) & (in_y <= Hm1) &
                 (in_x >= 0.0f) & (in_x <= Hm1);

    const float4* fm_b = sp.fm_b;
    float4* out_ptr = (float4*)(out + (size_t)roi * NCELL * NCH) + cell * NQ + cq;

    float4 v = make_float4(0.f, 0.f, 0.f, 0.f);
    if (valid) {
        float fy = floorf(in_y);
        float fx = floorf(in_x);
        float ly = in_y - fy;
        float lx = in_x - fx;
        // in-range ⇒ floor in [0,H-1]; ceil only needs upper clip
        int y0 = (int)fy;
        int x0 = (int)fx;
        int yc = (int)fminf(ceilf(in_y), Hm1);
        int xc = (int)fminf(ceilf(in_x), Hm1);

        const float4* row0 = fm_b + (size_t)y0 * W * NQ;
        const float4* row1 = fm_b + (size_t)yc * W * NQ;
        float4 tl = __ldg(row0 + x0 * NQ + cq);
        float4 tr = __ldg(row0 + xc * NQ + cq);
        float4 bl = __ldg(row1 + x0 * NQ + cq);
        float4 br = __ldg(row1 + xc * NQ + cq);

        float4 top, bot;
        top.x = fmaf(tr.x - tl.x, lx, tl.x);
        top.y = fmaf(tr.y - tl.y, lx, tl.y);
        top.z = fmaf(tr.z - tl.z, lx, tl.z);
        top.w = fmaf(tr.w - tl.w, lx, tl.w);
        bot.x = fmaf(br.x - bl.x, lx, bl.x);
        bot.y = fmaf(br.y - bl.y, lx, bl.y);
        bot.z = fmaf(br.z - bl.z, lx, bl.z);
        bot.w = fmaf(br.w - bl.w, lx, bl.w);
        v.x = fmaf(bot.x - top.x, ly, top.x);
        v.y = fmaf(bot.y - top.y, ly, top.y);
        v.z = fmaf(bot.z - top.z, ly, top.z);
        v.w = fmaf(bot.w - top.w, ly, top.w);
    }
    *out_ptr = v;
}

extern "C" void kernel_launch(void* const* d_in, const int* in_sizes, int n_in,
                              void* d_out, int out_size)
{
    const float* p2   = (const float*)d_in[0];
    const float* p3   = (const float*)d_in[1];
    const float* p4   = (const float*)d_in[2];
    const float* p5   = (const float*)d_in[3];
    const float* rois = (const float*)d_in[4];
    float* out = (float*)d_out;
    int n_rois = in_sizes[4] / 5;

    dim3 grid(n_rois, NGROUPS);
    roialign_kernel<<<grid, NQ * SLOTS>>>(p2, p3, p4, p5, rois, out);
}

// round 5
// speedup vs baseline: 1.2716x; 1.0151x over previous
#include <cuda_runtime.h>
#include <cuda_bf16.h>

#define OUT_SZ 7
#define NCELL (OUT_SZ * OUT_SZ)      // 49
#define NCH 256
#define NQ (NCH / 4)                 // 64 float4 per channel row
#define MAX_ROIS 1024

struct alignas(32) RoiP {
    float y_base, x_base, h_scale, w_scale;   // 16 B
    float Hm1;                                // H-1 == W-1
    int   W;
    const float4* fm_b;                       // resolved base (batch+level)
};

__device__ RoiP g_params[MAX_ROIS];

__global__ void decode_kernel(const float* __restrict__ p2,
                              const float* __restrict__ p3,
                              const float* __restrict__ p4,
                              const float* __restrict__ p5,
                              const float* __restrict__ rois,
                              int n_rois)
{
    int roi = blockIdx.x * blockDim.x + threadIdx.x;
    if (roi >= n_rois) return;

    // rois row: [batch, x1, y1, x2, y2]
    const float* r = rois + (size_t)roi * 5;
    float bf  = __ldg(r + 0);
    float rx1 = __ldg(r + 1), ry1 = __ldg(r + 2);
    float rx2 = __ldg(r + 3), ry2 = __ldg(r + 4);
    int b = (int)bf;

    float roi_w = rx2 - rx1;
    float roi_h = ry2 - ry1;
    float lvl = 4.0f + log2f(sqrtf(roi_h * roi_w) / 224.0f);
    int level = (int)rintf(lvl);
    level = level < 2 ? 2 : (level > 5 ? 5 : level);

    const float* fm;
    int H;
    float inv_stride;
    switch (level) {
        case 2: fm = p2; H = 256; inv_stride = 1.0f / 4.0f;  break;
        case 3: fm = p3; H = 128; inv_stride = 1.0f / 8.0f;  break;
        case 4: fm = p4; H = 64;  inv_stride = 1.0f / 16.0f; break;
        default: fm = p5; H = 32; inv_stride = 1.0f / 32.0f; break;
    }
    float Hm1 = (float)(H - 1);

    // crop_and_resize reads boxes as [y1,x1,y2,x2]; roi_align passes
    // [x1,y1,x2,y2]*(1/stride). So box_y1 = rx1/stride, box_x1 = ry1/stride.
    float by1 = rx1 * inv_stride;
    float bx1 = ry1 * inv_stride;
    float by2 = rx2 * inv_stride;
    float bx2 = ry2 * inv_stride;

    RoiP p;
    p.h_scale = (by2 - by1) * Hm1 * (1.0f / (float)(OUT_SZ - 1));
    p.w_scale = (bx2 - bx1) * Hm1 * (1.0f / (float)(OUT_SZ - 1));
    p.y_base  = by1 * Hm1;
    p.x_base  = bx1 * Hm1;
    p.Hm1     = Hm1;
    p.W       = H;
    p.fm_b    = (const float4*)(fm + (size_t)b * H * H * NCH);
    g_params[roi] = p;
}

__global__ __launch_bounds__(NQ * OUT_SZ, 4)
void gather_kernel(float* __restrict__ out)
{
    int roi = blockIdx.x;
    int tid = threadIdx.x;
    int cq   = tid & (NQ - 1);   // channel quad 0..63
    int j    = tid >> 6;         // column 0..6
    int i    = blockIdx.y;       // row 0..6

    RoiP p = g_params[roi];

    float Hm1 = p.Hm1;
    int   W   = p.W;
    float in_y = fmaf((float)i, p.h_scale, p.y_base);
    float in_x = fmaf((float)j, p.w_scale, p.x_base);
    bool valid = (in_y >= 0.0f) & (in_y <= Hm1) &
                 (in_x >= 0.0f) & (in_x <= Hm1);

    float4* out_ptr = (float4*)(out + (size_t)roi * NCELL * NCH)
                      + (i * OUT_SZ + j) * NQ + cq;

    float4 v = make_float4(0.f, 0.f, 0.f, 0.f);
    if (valid) {
        float fy = floorf(in_y);
        float fx = floorf(in_x);
        float ly = in_y - fy;
        float lx = in_x - fx;
        // in-range ⇒ floor in [0,H-1]; ceil only needs upper clip
        int y0 = (int)fy;
        int x0 = (int)fx;
        int yc = (int)fminf(ceilf(in_y), Hm1);
        int xc = (int)fminf(ceilf(in_x), Hm1);

        const float4* row0 = p.fm_b + (size_t)y0 * W * NQ;
        const float4* row1 = p.fm_b + (size_t)yc * W * NQ;
        float4 tl = __ldg(row0 + x0 * NQ + cq);
        float4 tr = __ldg(row0 + xc * NQ + cq);
        float4 bl = __ldg(row1 + x0 * NQ + cq);
        float4 br = __ldg(row1 + xc * NQ + cq);

        float4 top, bot;
        top.x = fmaf(tr.x - tl.x, lx, tl.x);
        top.y = fmaf(tr.y - tl.y, lx, tl.y);
        top.z = fmaf(tr.z - tl.z, lx, tl.z);
        top.w = fmaf(tr.w - tl.w, lx, tl.w);
        bot.x = fmaf(br.x - bl.x, lx, bl.x);
        bot.y = fmaf(br.y - bl.y, lx, bl.y);
        bot.z = fmaf(br.z - bl.z, lx, bl.z);
        bot.w = fmaf(br.w - bl.w, lx, bl.w);
        v.x = fmaf(bot.x - top.x, ly, top.x);
        v.y = fmaf(bot.y - top.y, ly, top.y);
        v.z = fmaf(bot.z - top.z, ly, top.z);
        v.w = fmaf(bot.w - top.w, ly, top.w);
    }
    *out_ptr = v;
}

extern "C" void kernel_launch(void* const* d_in, const int* in_sizes, int n_in,
                              void* d_out, int out_size)
{
    const float* p2   = (const float*)d_in[0];
    const float* p3   = (const float*)d_in[1];
    const float* p4   = (const float*)d_in[2];
    const float* p5   = (const float*)d_in[3];
    const float* rois = (const float*)d_in[4];
    float* out = (float*)d_out;
    int n_rois = in_sizes[4] / 5;

    int dec_threads = 256;
    int dec_blocks = (n_rois + dec_threads - 1) / dec_threads;
    decode_kernel<<<dec_blocks, dec_threads>>>(p2, p3, p4, p5, rois, n_rois);

    dim3 grid(n_rois, OUT_SZ);
    gather_kernel<<<grid, NQ * OUT_SZ>>>(out);
}